// round 6
// baseline (speedup 1.0000x reference)
#include <cuda_runtime.h>
#include <cuda_fp16.h>

// Problem constants
#define NXv 128
#define NYv 128
#define NZv 8
#define NVOX (NXv * NYv * NZv)   // 131072
#define NVIEW 6
#define NCH 64
#define HFv 116
#define WFv 200
#define FEAT_HW (HFv * WFv)      // 23200
#define IMG_W 1600.0f
#define IMG_H 928.0f

#define PTS_PER_BLK 64
#define DESC_STRIDE 7            // uint4 stride per point (6 views + 1 pad)

// Channel-last fp16 scratch: [V, HF, WF, C]  (17.8 MB). One tap = 128B line.
__device__ __align__(256) static __half g_feat_h[NVIEW * FEAT_HW * NCH];

// ---------------------------------------------------------------------------
// Kernel 1: transpose+convert [V,C,H,W] fp32 -> [V,H,W,C] fp16.
// ---------------------------------------------------------------------------
__global__ __launch_bounds__(256)
void convert_kernel(const float* __restrict__ xfov)
{
    __shared__ float tile[NCH][33];

    const int w0 = blockIdx.x * 32;
    const int vh = blockIdx.y;            // 0..695
    const int v  = vh / HFv;
    const int h  = vh - v * HFv;

    const int tx = threadIdx.x & 31;
    const int ty = threadIdx.x >> 5;      // 0..7

    const int w = w0 + tx;
    if (w < WFv) {
#pragma unroll
        for (int i = 0; i < 8; i++) {
            const int c = ty + i * 8;
            tile[c][tx] = xfov[((size_t)(v * NCH + c) * HFv + h) * WFv + w];
        }
    }
    __syncthreads();

    __half2* dst = (__half2*)g_feat_h;
#pragma unroll
    for (int j = 0; j < 4; j++) {
        const int ww = w0 + ty + 8 * j;
        if (ww < WFv) {
            const float a = tile[2 * tx + 0][ty + 8 * j];
            const float b = tile[2 * tx + 1][ty + 8 * j];
            dst[(size_t)(v * FEAT_HW + h * WFv + ww) * (NCH / 2) + tx] =
                __floats2half2_rn(a, b);
        }
    }
}

// ---------------------------------------------------------------------------
// Kernel 2: gather with block-cooperative projection.
// Phase 1: 256 threads compute 64 points x 6 views -> 16B descriptors in SMEM.
// Phase 2: 4 threads/point consume descriptors; taps from one base offset.
// ---------------------------------------------------------------------------
__device__ __forceinline__ void project_task(int task, int blk_p0,
                                             const float* __restrict__ points,
                                             const float* sM, uint4* sdesc)
{
    const int pl = task & (PTS_PER_BLK - 1);  // local point
    const int v  = task >> 6;                 // view 0..5

    const int p = blk_p0 + pl;                // output-linear voxel
    const int z = p & (NZv - 1);
    const int y = (p >> 3) & (NYv - 1);
    const int x = p >> 10;
    const int n = (z * NYv + y) * NXv + x;

    const float pxw = __ldg(points + n * 3 + 0);
    const float pyw = __ldg(points + n * 3 + 1);
    const float pzw = __ldg(points + n * 3 + 2);

    const float* M = &sM[v * 16];
    const float cx = fmaf(M[0], pxw, fmaf(M[1], pyw, fmaf(M[2],  pzw, M[3])));
    const float cy = fmaf(M[4], pxw, fmaf(M[5], pyw, fmaf(M[6],  pzw, M[7])));
    const float d  = fmaf(M[8], pxw, fmaf(M[9], pyw, fmaf(M[10], pzw, M[11])));

    const float ds = (fabsf(d) > 1e-6f) ? d : 1e-6f;
    const float r  = __fdividef(1.0f, ds);
    const float u  = cx * r;
    const float vv = cy * r;

    const bool valid = (d > 0.0f) & (u > 0.0f) & (u < IMG_W)
                                  & (vv > 0.0f) & (vv < IMG_H);

    uint4 desc;
    desc.x = 0xFFFFFFFFu;
    desc.y = 0u; desc.z = 0u; desc.w = 0u;

    if (valid) {
        // Exact power-of-2 scale: WF/IMG_W = HF/IMG_H = 0.125
        const float fx = fmaf(u,  0.125f, -0.5f);   // (-0.5, 199.5)
        const float fy = fmaf(vv, 0.125f, -0.5f);   // (-0.5, 115.5)
        const float x0f = floorf(fx);
        const float y0f = floorf(fy);
        const int x0 = (int)x0f;   // [-1, 199]
        const int y0 = (int)y0f;   // [-1, 115]
        const float wx1 = fx - x0f;
        const float wy1 = fy - y0f;

        // Clamp base so all 4 taps are in-bounds; fold edge zeroing / tap
        // shifting into the weights (identical to zero-padded bilinear).
        const int bx = min(max(x0, 0), WFv - 2);
        const int by = min(max(y0, 0), HFv - 2);
        const float wl = (x0 < 0) ? wx1 : ((x0 >= WFv - 1) ? 0.0f : 1.0f - wx1);
        const float wr = (x0 < 0) ? 0.0f : ((x0 >= WFv - 1) ? 1.0f - wx1 : wx1);
        const float wt = (y0 < 0) ? wy1 : ((y0 >= HFv - 1) ? 0.0f : 1.0f - wy1);
        const float wb = (y0 < 0) ? 0.0f : ((y0 >= HFv - 1) ? 1.0f - wy1 : wy1);

        const __half2 h0 = __floats2half2_rn(wl * wt, wr * wt); // w00,w10
        const __half2 h1 = __floats2half2_rn(wl * wb, wr * wb); // w01,w11

        desc.x = (unsigned)((v * FEAT_HW + by * WFv + bx) * NCH); // halves
        desc.y = *(const unsigned*)&h0;
        desc.z = *(const unsigned*)&h1;
    }
    sdesc[pl * DESC_STRIDE + v] = desc;
}

__device__ __forceinline__ void hcomb(float* acc,
                                      const uint4& a00, const uint4& a10,
                                      const uint4& a01, const uint4& a11,
                                      __half2 w00, __half2 w10,
                                      __half2 w01, __half2 w11)
{
    const __half2* f00 = (const __half2*)&a00;
    const __half2* f10 = (const __half2*)&a10;
    const __half2* f01 = (const __half2*)&a01;
    const __half2* f11 = (const __half2*)&a11;
#pragma unroll
    for (int k = 0; k < 4; k++) {
        __half2 s = __hmul2(f00[k], w00);
        s = __hfma2(f10[k], w10, s);
        s = __hfma2(f01[k], w01, s);
        s = __hfma2(f11[k], w11, s);
        const float2 sf = __half22float2(s);
        acc[2 * k + 0] += sf.x;
        acc[2 * k + 1] += sf.y;
    }
}

__global__ __launch_bounds__(256)
void gather_kernel(const float* __restrict__ points,
                   const float* __restrict__ proj,
                   float* __restrict__ out)
{
    __shared__ float sM[NVIEW * 16];
    __shared__ uint4 sdesc[PTS_PER_BLK * DESC_STRIDE];

    if (threadIdx.x < NVIEW * 16) sM[threadIdx.x] = proj[threadIdx.x];
    __syncthreads();

    const int blk_p0 = blockIdx.x * PTS_PER_BLK;

    // Phase 1: 384 projection tasks over 256 threads
    project_task(threadIdx.x, blk_p0, points, sM, sdesc);
    if (threadIdx.x < PTS_PER_BLK * NVIEW - 256)
        project_task(256 + threadIdx.x, blk_p0, points, sM, sdesc);
    __syncthreads();

    // Phase 2: 4 threads per point, 16 channels each
    const int pl = threadIdx.x >> 2;          // local point 0..63
    const int q  = threadIdx.x & 3;           // channel quarter
    const int p  = blk_p0 + pl;
    const int coff = q * 16;                  // halves

    float acc[16];
#pragma unroll
    for (int i = 0; i < 16; i++) acc[i] = 0.0f;
    int cnt = 0;

#pragma unroll 1
    for (int v = 0; v < NVIEW; v++) {
        const uint4 dsc = sdesc[pl * DESC_STRIDE + v];
        if (dsc.x == 0xFFFFFFFFu) continue;

        const __half* base = g_feat_h + dsc.x + coff;
        const uint4* t00 = (const uint4*)(base);
        const uint4* t10 = (const uint4*)(base + NCH);
        const uint4* t01 = (const uint4*)(base + WFv * NCH);
        const uint4* t11 = (const uint4*)(base + (WFv + 1) * NCH);

        const uint4 a00 = __ldg(t00 + 0), b00 = __ldg(t00 + 1);
        const uint4 a10 = __ldg(t10 + 0), b10 = __ldg(t10 + 1);
        const uint4 a01 = __ldg(t01 + 0), b01 = __ldg(t01 + 1);
        const uint4 a11 = __ldg(t11 + 0), b11 = __ldg(t11 + 1);

        const __half2 wpair0 = *(const __half2*)&dsc.y;  // (w00, w10)
        const __half2 wpair1 = *(const __half2*)&dsc.z;  // (w01, w11)
        const __half2 hw00 = __low2half2(wpair0);
        const __half2 hw10 = __high2half2(wpair0);
        const __half2 hw01 = __low2half2(wpair1);
        const __half2 hw11 = __high2half2(wpair1);

        hcomb(acc + 0, a00, a10, a01, a11, hw00, hw10, hw01, hw11);
        hcomb(acc + 8, b00, b10, b01, b11, hw00, hw10, hw01, hw11);
        cnt++;
    }

    const float inv = (cnt > 0) ? (1.0f / (float)cnt) : 0.0f;
    const int cbase = q * 16;
#pragma unroll
    for (int j = 0; j < 16; j++) {
        out[(size_t)(cbase + j) * NVOX + p] = acc[j] * inv;
    }
}

extern "C" void kernel_launch(void* const* d_in, const int* in_sizes, int n_in,
                              void* d_out, int out_size)
{
    const float* x_fov  = (const float*)d_in[0];  // [1,6,64,116,200]
    const float* points = (const float*)d_in[1];  // [131072,3]
    const float* proj   = (const float*)d_in[2];  // [6,4,4]
    float* out = (float*)d_out;                   // [1,64,128,128,8]

    {
        dim3 blk(256);
        dim3 grd((WFv + 31) / 32, NVIEW * HFv);   // (7, 696)
        convert_kernel<<<grd, blk>>>(x_fov);
    }
    {
        const int blocks = NVOX / PTS_PER_BLK;    // 2048
        gather_kernel<<<blocks, 256>>>(points, proj, out);
    }
}

// round 7
// speedup vs baseline: 1.0653x; 1.0653x over previous
#include <cuda_runtime.h>
#include <cuda_fp16.h>

// Problem constants
#define NXv 128
#define NYv 128
#define NZv 8
#define NVOX (NXv * NYv * NZv)   // 131072
#define NVIEW 6
#define NCH 64
#define HFv 116
#define WFv 200
#define FEAT_HW (HFv * WFv)      // 23200
#define IMG_W 1600.0f
#define IMG_H 928.0f

// Channel-last fp16 scratch: [V, HF, WF, C]  (17.8 MB). One tap = 128B line.
__device__ __align__(256) static __half g_feat_h[NVIEW * FEAT_HW * NCH];

// ---------------------------------------------------------------------------
// Kernel 1: transpose+convert [V,C,H,W] fp32 -> [V,H,W,C] fp16.
// ---------------------------------------------------------------------------
__global__ __launch_bounds__(256)
void convert_kernel(const float* __restrict__ xfov)
{
    __shared__ float tile[NCH][33];

    const int w0 = blockIdx.x * 32;
    const int vh = blockIdx.y;            // 0..695
    const int v  = vh / HFv;
    const int h  = vh - v * HFv;

    const int tx = threadIdx.x & 31;
    const int ty = threadIdx.x >> 5;      // 0..7

    const int w = w0 + tx;
    if (w < WFv) {
#pragma unroll
        for (int i = 0; i < 8; i++) {
            const int c = ty + i * 8;
            tile[c][tx] = xfov[((size_t)(v * NCH + c) * HFv + h) * WFv + w];
        }
    }
    __syncthreads();

    __half2* dst = (__half2*)g_feat_h;
#pragma unroll
    for (int j = 0; j < 4; j++) {
        const int ww = w0 + ty + 8 * j;
        if (ww < WFv) {
            const float a = tile[2 * tx + 0][ty + 8 * j];
            const float b = tile[2 * tx + 1][ty + 8 * j];
            dst[(size_t)(v * FEAT_HW + h * WFv + ww) * (NCH / 2) + tx] =
                __floats2half2_rn(a, b);
        }
    }
}

// ---------------------------------------------------------------------------
// Projection of one (point, view) -> 32-bit base offset (halves) + fp16 weights.
// Edge handling folded into weights; base clamped so all 4 taps are in-bounds.
// off == 0xFFFFFFFF marks invalid.
// ---------------------------------------------------------------------------
__device__ __forceinline__ void project_v(int v,
                                          float pxw, float pyw, float pzw,
                                          const float* sM,
                                          unsigned& off, unsigned& w0, unsigned& w1)
{
    const float* M = &sM[v * 16];
    const float cx = fmaf(M[0], pxw, fmaf(M[1], pyw, fmaf(M[2],  pzw, M[3])));
    const float cy = fmaf(M[4], pxw, fmaf(M[5], pyw, fmaf(M[6],  pzw, M[7])));
    const float d  = fmaf(M[8], pxw, fmaf(M[9], pyw, fmaf(M[10], pzw, M[11])));

    const float ds = (fabsf(d) > 1e-6f) ? d : 1e-6f;
    const float r  = __fdividef(1.0f, ds);
    const float u  = cx * r;
    const float vv = cy * r;

    const bool valid = (d > 0.0f) & (u > 0.0f) & (u < IMG_W)
                                  & (vv > 0.0f) & (vv < IMG_H);

    off = 0xFFFFFFFFu;
    w0 = 0u;
    w1 = 0u;

    if (valid) {
        // Exact power-of-2 scale: WF/IMG_W = HF/IMG_H = 0.125
        const float fx = fmaf(u,  0.125f, -0.5f);   // (-0.5, 199.5)
        const float fy = fmaf(vv, 0.125f, -0.5f);   // (-0.5, 115.5)
        const float x0f = floorf(fx);
        const float y0f = floorf(fy);
        const int x0 = (int)x0f;   // [-1, 199]
        const int y0 = (int)y0f;   // [-1, 115]
        const float wx1 = fx - x0f;
        const float wy1 = fy - y0f;

        const int bx = min(max(x0, 0), WFv - 2);
        const int by = min(max(y0, 0), HFv - 2);
        const float wl = (x0 < 0) ? wx1 : ((x0 >= WFv - 1) ? 0.0f : 1.0f - wx1);
        const float wr = (x0 < 0) ? 0.0f : ((x0 >= WFv - 1) ? 1.0f - wx1 : wx1);
        const float wt = (y0 < 0) ? wy1 : ((y0 >= HFv - 1) ? 0.0f : 1.0f - wy1);
        const float wb = (y0 < 0) ? 0.0f : ((y0 >= HFv - 1) ? 1.0f - wy1 : wy1);

        const __half2 h0 = __floats2half2_rn(wl * wt, wr * wt); // (w00, w10)
        const __half2 h1 = __floats2half2_rn(wl * wb, wr * wb); // (w01, w11)

        off = (unsigned)((v * FEAT_HW + by * WFv + bx) * NCH);  // in halves
        w0  = *(const unsigned*)&h0;
        w1  = *(const unsigned*)&h1;
    }
}

__device__ __forceinline__ void hcomb(float* acc,
                                      const uint4& a00, const uint4& a10,
                                      const uint4& a01, const uint4& a11,
                                      __half2 w00, __half2 w10,
                                      __half2 w01, __half2 w11)
{
    const __half2* f00 = (const __half2*)&a00;
    const __half2* f10 = (const __half2*)&a10;
    const __half2* f01 = (const __half2*)&a01;
    const __half2* f11 = (const __half2*)&a11;
#pragma unroll
    for (int k = 0; k < 4; k++) {
        __half2 s = __hmul2(f00[k], w00);
        s = __hfma2(f10[k], w10, s);
        s = __hfma2(f01[k], w01, s);
        s = __hfma2(f11[k], w11, s);
        const float2 sf = __half22float2(s);
        acc[2 * k + 0] += sf.x;
        acc[2 * k + 1] += sf.y;
    }
}

// ---------------------------------------------------------------------------
// Kernel 2: gather. 4 threads/point (16 ch each). Projection dedup'd within
// the quad via warp shuffle: lane q computes views {q, 4+(q&1)}.
// ---------------------------------------------------------------------------
__global__ __launch_bounds__(256)
void gather_kernel(const float* __restrict__ points,
                   const float* __restrict__ proj,
                   float* __restrict__ out)
{
    __shared__ float sM[NVIEW * 16];
    if (threadIdx.x < NVIEW * 16) sM[threadIdx.x] = proj[threadIdx.x];
    __syncthreads();

    const int t    = blockIdx.x * blockDim.x + threadIdx.x; // 0..524287
    const int p    = t >> 2;                                // voxel (output-linear)
    const int q    = t & 3;                                 // channel quarter
    const int lane = threadIdx.x & 31;
    const int qbase = lane & ~3;                            // first lane of quad

    const int z = p & (NZv - 1);
    const int y = (p >> 3) & (NYv - 1);
    const int x = p >> 10;
    const int n = (z * NYv + y) * NXv + x;

    const float pxw = __ldg(points + n * 3 + 0);
    const float pyw = __ldg(points + n * 3 + 1);
    const float pzw = __ldg(points + n * 3 + 2);

    // Each lane projects 2 views for its own point.
    unsigned offA, wA0, wA1;                 // view q
    unsigned offB, wB0, wB1;                 // view 4+(q&1)
    project_v(q, pxw, pyw, pzw, sM, offA, wA0, wA1);
    project_v(4 + (q & 1), pxw, pyw, pzw, sM, offB, wB0, wB1);

    float acc[16];
#pragma unroll
    for (int i = 0; i < 16; i++) acc[i] = 0.0f;
    int cnt = 0;

#pragma unroll
    for (int v = 0; v < NVIEW; v++) {
        const int src = qbase | (v & 3);     // owner lane of view v in quad
        const unsigned off = __shfl_sync(0xFFFFFFFFu, (v < 4) ? offA : offB, src);
        const unsigned w0  = __shfl_sync(0xFFFFFFFFu, (v < 4) ? wA0  : wB0,  src);
        const unsigned w1  = __shfl_sync(0xFFFFFFFFu, (v < 4) ? wA1  : wB1,  src);

        if (off != 0xFFFFFFFFu) {
            const __half* bp = g_feat_h + off + q * 16;

            const uint4 a00 = __ldg((const uint4*)(bp));
            const uint4 b00 = __ldg((const uint4*)(bp + 8));
            const uint4 a10 = __ldg((const uint4*)(bp + NCH));
            const uint4 b10 = __ldg((const uint4*)(bp + NCH + 8));
            const uint4 a01 = __ldg((const uint4*)(bp + WFv * NCH));
            const uint4 b01 = __ldg((const uint4*)(bp + WFv * NCH + 8));
            const uint4 a11 = __ldg((const uint4*)(bp + (WFv + 1) * NCH));
            const uint4 b11 = __ldg((const uint4*)(bp + (WFv + 1) * NCH + 8));

            const __half2 wp0 = *(const __half2*)&w0;   // (w00, w10)
            const __half2 wp1 = *(const __half2*)&w1;   // (w01, w11)
            const __half2 hw00 = __low2half2(wp0);
            const __half2 hw10 = __high2half2(wp0);
            const __half2 hw01 = __low2half2(wp1);
            const __half2 hw11 = __high2half2(wp1);

            hcomb(acc + 0, a00, a10, a01, a11, hw00, hw10, hw01, hw11);
            hcomb(acc + 8, b00, b10, b01, b11, hw00, hw10, hw01, hw11);
            cnt++;
        }
    }

    const float inv = (cnt > 0) ? (1.0f / (float)cnt) : 0.0f;
    const int cbase = q * 16;
#pragma unroll
    for (int j = 0; j < 16; j++) {
        out[(size_t)(cbase + j) * NVOX + p] = acc[j] * inv;
    }
}

extern "C" void kernel_launch(void* const* d_in, const int* in_sizes, int n_in,
                              void* d_out, int out_size)
{
    const float* x_fov  = (const float*)d_in[0];  // [1,6,64,116,200]
    const float* points = (const float*)d_in[1];  // [131072,3]
    const float* proj   = (const float*)d_in[2];  // [6,4,4]
    float* out = (float*)d_out;                   // [1,64,128,128,8]

    {
        dim3 blk(256);
        dim3 grd((WFv + 31) / 32, NVIEW * HFv);   // (7, 696)
        convert_kernel<<<grd, blk>>>(x_fov);
    }
    {
        const int threads = 256;
        const int blocks  = (NVOX * 4) / threads; // 2048
        gather_kernel<<<blocks, threads>>>(points, proj, out);
    }
}